// round 14
// baseline (speedup 1.0000x reference)
#include <cuda_runtime.h>
#include <math.h>

#define Bb      256
#define Nn      8192
#define SD      14
#define ROWS    256
#define THREADS 256
#define CHUNKS  32
#define NTILES  (Bb * CHUNKS)     // 8192
#define GRID    296               // block 0 = argmin+BC, 1..295 = tile workers
#define WORKERS (GRID - 1)        // 295

#define TILE_F4      ((ROWS * SD) / 4)   // 896
#define MAIN_FLOATS  (ROWS * SD)         // 3584
#define HALO_LO_OFF  MAIN_FLOATS         // 3584 (14 floats)
#define HALO_HI_OFF  (MAIN_FLOATS + 14)  // 3598
#define BUF_FLOATS   3616

// accumulators: 0=weighted data, 1=phys, 2=quat, 3=massflow, 4=bc
__device__ double       g_acc[5];
__device__ unsigned int g_done;

// ---------------------------------------------------------------------------
// register-resident tile loads (coalesced LDG.128 + halo LDG.32)
// ---------------------------------------------------------------------------
__device__ __forceinline__ void load_pred(int tile, const float* __restrict__ pred,
                                          int tid, float4 p[4],
                                          float& hlo, float& hhi)
{
    const int b = tile >> 5, chunk = tile & (CHUNKS - 1);
    const size_t base = ((size_t)b * Nn + (size_t)chunk * ROWS) * SD;
    const float4* p4 = (const float4*)(pred + base);
    p[0] = p4[tid];
    p[1] = p4[tid + 256];
    p[2] = p4[tid + 512];
    if (tid < TILE_F4 - 768) p[3] = p4[tid + 768];
    if (chunk > 0 && tid >= 128 && tid < 128 + SD)
        hlo = pred[base - SD + (tid - 128)];
    if (chunk < CHUNKS - 1 && tid >= 160 && tid < 160 + SD)
        hhi = pred[base + MAIN_FLOATS + (tid - 160)];
}

__device__ __forceinline__ void load_true(int tile, const float* __restrict__ truev,
                                          int tid, float4 tt[4])
{
    const int b = tile >> 5, chunk = tile & (CHUNKS - 1);
    const size_t base = ((size_t)b * Nn + (size_t)chunk * ROWS) * SD;
    const float4* t4 = (const float4*)(truev + base);
    tt[0] = t4[tid];
    tt[1] = t4[tid + 256];
    tt[2] = t4[tid + 512];
    if (tid < TILE_F4 - 768) tt[3] = t4[tid + 768];
}

__device__ __forceinline__ float4 load_ctrl(int tile, const float* __restrict__ ctrl,
                                            int tid)
{
    const int b = tile >> 5, chunk = tile & (CHUNKS - 1);
    const size_t rowoff = (size_t)b * Nn + (size_t)chunk * ROWS;
    return ((const float4*)(ctrl + rowoff * 4))[tid];
}

__device__ __forceinline__ void store_pred(float* buf, int tid, const float4 p[4],
                                           float hlo, float hhi)
{
    float4* b4 = (float4*)buf;
    b4[tid]       = p[0];
    b4[tid + 256] = p[1];
    b4[tid + 512] = p[2];
    if (tid < TILE_F4 - 768) b4[tid + 768] = p[3];
    if (tid >= 128 && tid < 128 + SD) buf[HALO_LO_OFF + (tid - 128)] = hlo;
    if (tid >= 160 && tid < 160 + SD) buf[HALO_HI_OFF + (tid - 160)] = hhi;
}

// ---------------------------------------------------------------------------
// Single persistent kernel; all streams register-pipelined one tile ahead.
//   block 0       : argmin|t| + boundary-condition loss
//   blocks 1..295 : tile streaming (data/phys/quat/massflow)
//   last ticket   : finalize -> out[6], reset accumulators for next replay
// ---------------------------------------------------------------------------
__global__ __launch_bounds__(THREADS)
void k_main(const float* __restrict__ pred,
            const float* __restrict__ truev,
            const float* __restrict__ t,
            const float* __restrict__ ctrl,
            float* __restrict__ out)
{
    __shared__ __align__(16) float buf[BUF_FLOATS];
    __shared__ double red[THREADS / 32][5];

    const int tid = threadIdx.x;
    float wD = 0.f, sP = 0.f, sQ = 0.f, sMF = 0.f, sBC = 0.f;

    if (blockIdx.x == 0) {
        // ---- argmin |t[0,:,0]| ----
        __shared__ float svals[THREADS];
        __shared__ int   sidx[THREADS];
        const float4* t4 = (const float4*)t;
        float best = 3.402823466e+38f;
        int   bi   = 0;
        #pragma unroll
        for (int j = 0; j < 8; j++) {
            float4 v = t4[tid * 8 + j];
            float a[4] = { fabsf(v.x), fabsf(v.y), fabsf(v.z), fabsf(v.w) };
            #pragma unroll
            for (int k = 0; k < 4; k++) {
                int idx = tid * 32 + j * 4 + k;
                if (a[k] < best) { best = a[k]; bi = idx; }
            }
        }
        svals[tid] = best;  sidx[tid] = bi;
        __syncthreads();
        for (int s = THREADS / 2; s > 0; s >>= 1) {
            if (tid < s) {
                float v2 = svals[tid + s];
                int   i2 = sidx[tid + s];
                if (v2 < svals[tid] || (v2 == svals[tid] && i2 < sidx[tid])) {
                    svals[tid] = v2;  sidx[tid] = i2;
                }
            }
            __syncthreads();
        }
        const int tidx = sidx[0];

        // ---- boundary-condition loss: thread b handles batch b ----
        const float* pr = pred  + ((size_t)tid * Nn + tidx) * SD;
        const float* tr = truev + ((size_t)tid * Nn + tidx) * SD;
        #pragma unroll
        for (int i = 0; i < SD; i++) {
            float d = pr[i] - tr[i];
            sBC = fmaf(d, d, sBC);
        }
    } else {
        // ---- tile workers ----
        const int wid = blockIdx.x - 1;

        float4 p[4], tt[4];
        float  hlo = 0.f, hhi = 0.f;
        load_pred(wid, pred, tid, p, hlo, hhi);
        load_true(wid, truev, tid, tt);
        float4 u4 = load_ctrl(wid, ctrl, tid);

        #pragma unroll 1
        for (int tile = wid; tile < NTILES; tile += WORKERS) {
            __syncthreads();                    // buf free (prev FD done)
            store_pred(buf, tid, p, hlo, hhi);

            const int chunk = tile & (CHUNKS - 1);
            const int n0    = chunk * ROWS;

            // ---- weighted data loss: all operands already in registers ----
            #pragma unroll
            for (int j = 0; j < 4; j++) {
                const int i = tid + j * 256;
                if (j == 3 && i >= TILE_F4) break;
                unsigned e = 4u * (unsigned)i;
                unsigned r = e / 14u;
                unsigned c = e - r * 14u;
                const float pe[4] = { p[j].x, p[j].y, p[j].z, p[j].w };
                const float te[4] = { tt[j].x, tt[j].y, tt[j].z, tt[j].w };
                #pragma unroll
                for (int k = 0; k < 4; k++) {
                    float d = pe[k] - te[k];
                    float w = (c < 6u) ? (1.0f / 6.0f)
                            : ((c == 13u) ? 1.0f : (1.0f / 7.0f));
                    wD = fmaf(d * d, w, wD);
                    if (++c == 14u) { c = 0u; ++r; }
                }
            }

            const float4 cu4 = u4;              // current tile's control

            // ---- prefetch ALL streams for tile + WORKERS ----
            if (tile + WORKERS < NTILES) {
                hlo = hhi = 0.f;
                load_pred(tile + WORKERS, pred, tid, p, hlo, hhi);
                load_true(tile + WORKERS, truev, tid, tt);
                u4 = load_ctrl(tile + WORKERS, ctrl, tid);
            }

            __syncthreads();                    // buf filled

            // ---- per-row physics from smem ----
            const int n = n0 + tid;
            const float* s = buf + tid * SD;

            float sr[SD];
            {
                const float2* s2 = (const float2*)s;
                #pragma unroll
                for (int k = 0; k < 7; k++) {
                    float2 v = s2[k];
                    sr[2 * k] = v.x;  sr[2 * k + 1] = v.y;
                }
            }

            const bool fwd = (n == 0), bwd = (n == Nn - 1);
            const float* hip = (tid < ROWS - 1) ? (buf + (tid + 1) * SD)
                                                : (buf + HALO_HI_OFF);
            const float* lop = (tid > 0)        ? (buf + (tid - 1) * SD)
                                                : (buf + HALO_LO_OFF);
            if (fwd) lop = s;
            if (bwd) hip = s;

            float ta, tb2;
            if (fwd)      { ta = t[0];      tb2 = t[1];      }
            else if (bwd) { ta = t[Nn - 2]; tb2 = t[Nn - 1]; }
            else          { ta = t[n - 1];  tb2 = t[n + 1];  }
            const float inv_dt = 1.0f / (tb2 - ta + 1e-12f);

            const float q0 = sr[6], q1 = sr[7], q2 = sr[8], q3 = sr[9];
            const float qn  = sqrtf(q0 * q0 + q1 * q1 + q2 * q2 + q3 * q3);
            const float dqn = qn - 1.0f;
            sQ += dqn * dqn;

            if (n < Nn - 1) {
                float dmf = hip[13] - sr[13];
                if (dmf > 0.f) sMF += dmf;
            }

            const float vx = sr[3],  vy = sr[4],  vz = sr[5];
            const float wx = sr[10], wy = sr[11], wz = sr[12];
            const float thrust = cu4.x * 1000000.0f;
            const float bzx = 2.0f * (q1 * q3 + q0 * q2);
            const float bzy = 2.0f * (q2 * q3 - q0 * q1);
            const float bzz = 1.0f - 2.0f * (q1 * q1 + q2 * q2);
            const float speed = sqrtf(vx * vx + vy * vy + vz * vz + 1e-12f);
            const float dragc = -0.30625f * speed;
            const float invm  = 1.0f / sr[13];

            float dyn[SD];
            dyn[0]  = vx; dyn[1] = vy; dyn[2] = vz;
            dyn[3]  = (thrust * bzx + dragc * vx) * invm;
            dyn[4]  = (thrust * bzy + dragc * vy) * invm;
            dyn[5]  = (thrust * bzz + dragc * vz) * invm - 9.80665f;
            dyn[6]  = 0.5f * (-q1 * wx - q2 * wy - q3 * wz);
            dyn[7]  = 0.5f * ( q0 * wx + q2 * wz - q3 * wy);
            dyn[8]  = 0.5f * ( q0 * wy - q1 * wz + q3 * wx);
            dyn[9]  = 0.5f * ( q0 * wz + q1 * wy - q2 * wx);
            dyn[10] = (cu4.y * 10000.0f + 4000.0f * wy * wz) * (1.0f / 5000.0f);
            dyn[11] = (cu4.z * 10000.0f - 4000.0f * wz * wx) * (1.0f / 5000.0f);
            dyn[12] = (cu4.w * 10000.0f) * (1.0f / 1000.0f);
            dyn[13] = -thrust * (1.0f / (300.0f * 9.80665f));

            float sPl = 0.f;
            #pragma unroll
            for (int i = 0; i < SD; i++) {
                float rr = (hip[i] - lop[i]) * inv_dt - dyn[i];
                sPl = fmaf(rr, rr, sPl);
            }
            sP += sPl;
        }
    }

    // ---- reduction: fp32 intra-warp, fp64 cross-warp + global atomics ----
    float vf[5] = { wD, sP, sQ, sMF, sBC };
    const int lane = tid & 31, warp = tid >> 5;
    #pragma unroll
    for (int off = 16; off > 0; off >>= 1)
        #pragma unroll
        for (int j = 0; j < 5; j++)
            vf[j] += __shfl_down_sync(0xffffffffu, vf[j], off);
    if (lane == 0)
        #pragma unroll
        for (int j = 0; j < 5; j++) red[warp][j] = (double)vf[j];
    __syncthreads();

    if (warp == 0) {
        double vd[5];
        #pragma unroll
        for (int j = 0; j < 5; j++)
            vd[j] = (lane < THREADS / 32) ? red[lane][j] : 0.0;
        #pragma unroll
        for (int off = 4; off > 0; off >>= 1)
            #pragma unroll
            for (int j = 0; j < 5; j++)
                vd[j] += __shfl_down_sync(0xffffffffu, vd[j], off);
        if (lane == 0) {
            #pragma unroll
            for (int j = 0; j < 5; j++)
                atomicAdd(&g_acc[j], vd[j]);

            __threadfence();
            unsigned int ticket = atomicAdd(&g_done, 1u);
            if (ticket == GRID - 1) {
                const double BN = (double)Bb * (double)Nn;
                double L_data = g_acc[0] / BN;
                double L_phys = g_acc[1] / (BN * 14.0);
                double L_quat = g_acc[2] / BN;
                double L_mf   = g_acc[3] / ((double)Bb * (double)(Nn - 1));
                double L_bc   = g_acc[4] / ((double)Bb * 14.0);
                double total  = L_data + 0.1 * L_phys + L_bc
                              + 0.01 * L_quat + 0.01 * L_mf;
                out[0] = (float)total;
                out[1] = (float)L_data;
                out[2] = (float)L_phys;
                out[3] = (float)L_bc;
                out[4] = (float)L_quat;
                out[5] = (float)L_mf;
                // reset for next graph replay
                #pragma unroll
                for (int j = 0; j < 5; j++) g_acc[j] = 0.0;
                g_done = 0u;
            }
        }
    }
}

// ---------------------------------------------------------------------------
extern "C" void kernel_launch(void* const* d_in, const int* in_sizes, int n_in,
                              void* d_out, int out_size)
{
    const float* pred = (const float*)d_in[0];
    const float* tru  = (const float*)d_in[1];
    const float* t    = (const float*)d_in[2];
    const float* ctrl = (const float*)d_in[3];
    float* out = (float*)d_out;

    k_main<<<GRID, THREADS>>>(pred, tru, t, ctrl, out);
}

// round 15
// speedup vs baseline: 1.0276x; 1.0276x over previous
#include <cuda_runtime.h>
#include <math.h>

#define Bb      256
#define Nn      8192
#define SD      14
#define ROWS    256
#define THREADS 256
#define CHUNKS  32
#define NTILES  (Bb * CHUNKS)     // 8192
#define GRID    592               // 4 blocks/SM; block 0 = argmin+BC
#define WORKERS (GRID - 1)        // 591

#define TILE_F4      ((ROWS * SD) / 4)   // 896
#define MAIN_FLOATS  (ROWS * SD)         // 3584
#define HALO_LO_OFF  MAIN_FLOATS         // 3584 (14 floats)
#define HALO_HI_OFF  (MAIN_FLOATS + 14)  // 3598
#define BUF_FLOATS   3616

// accumulators: 0=weighted data, 1=phys, 2=quat, 3=massflow, 4=bc
__device__ double       g_acc[5];
__device__ unsigned int g_done;

// ---------------------------------------------------------------------------
__device__ __forceinline__ void load_pred(int tile, const float* __restrict__ pred,
                                          int tid, float4 p[4],
                                          float& hlo, float& hhi)
{
    const int b = tile >> 5, chunk = tile & (CHUNKS - 1);
    const size_t base = ((size_t)b * Nn + (size_t)chunk * ROWS) * SD;
    const float4* p4 = (const float4*)(pred + base);
    p[0] = p4[tid];
    p[1] = p4[tid + 256];
    p[2] = p4[tid + 512];
    if (tid < TILE_F4 - 768) p[3] = p4[tid + 768];
    if (chunk > 0 && tid >= 128 && tid < 128 + SD)
        hlo = pred[base - SD + (tid - 128)];
    if (chunk < CHUNKS - 1 && tid >= 160 && tid < 160 + SD)
        hhi = pred[base + MAIN_FLOATS + (tid - 160)];
}

__device__ __forceinline__ void store_pred(float* buf, int tid, const float4 p[4],
                                           float hlo, float hhi)
{
    float4* b4 = (float4*)buf;
    b4[tid]       = p[0];
    b4[tid + 256] = p[1];
    b4[tid + 512] = p[2];
    if (tid < TILE_F4 - 768) b4[tid + 768] = p[3];
    if (tid >= 128 && tid < 128 + SD) buf[HALO_LO_OFF + (tid - 128)] = hlo;
    if (tid >= 160 && tid < 160 + SD) buf[HALO_HI_OFF + (tid - 160)] = hhi;
}

// paired smem read helper (8B-aligned everywhere: all row offsets are 56B multiples)
__device__ __forceinline__ float2 lds2(const float* p, int i) {
    return *(const float2*)(p + i);
}

// ---------------------------------------------------------------------------
// Single persistent kernel, 4 blocks/SM.
//   block 0       : argmin|t| + boundary-condition loss
//   blocks 1..591 : tile streaming (data/phys/quat/massflow)
//   last ticket   : finalize -> out[6], reset accumulators for next replay
// ---------------------------------------------------------------------------
__global__ __launch_bounds__(THREADS, 4)
void k_main(const float* __restrict__ pred,
            const float* __restrict__ truev,
            const float* __restrict__ t,
            const float* __restrict__ ctrl,
            float* __restrict__ out)
{
    __shared__ __align__(16) float buf[BUF_FLOATS];
    __shared__ double red[THREADS / 32][5];

    const int tid = threadIdx.x;
    float wD = 0.f, sP = 0.f, sQ = 0.f, sMF = 0.f, sBC = 0.f;

    if (blockIdx.x == 0) {
        // ---- argmin |t[0,:,0]| ----
        __shared__ float svals[THREADS];
        __shared__ int   sidx[THREADS];
        const float4* t4 = (const float4*)t;
        float best = 3.402823466e+38f;
        int   bi   = 0;
        #pragma unroll
        for (int j = 0; j < 8; j++) {
            float4 v = t4[tid * 8 + j];
            float a[4] = { fabsf(v.x), fabsf(v.y), fabsf(v.z), fabsf(v.w) };
            #pragma unroll
            for (int k = 0; k < 4; k++) {
                int idx = tid * 32 + j * 4 + k;
                if (a[k] < best) { best = a[k]; bi = idx; }
            }
        }
        svals[tid] = best;  sidx[tid] = bi;
        __syncthreads();
        for (int s = THREADS / 2; s > 0; s >>= 1) {
            if (tid < s) {
                float v2 = svals[tid + s];
                int   i2 = sidx[tid + s];
                if (v2 < svals[tid] || (v2 == svals[tid] && i2 < sidx[tid])) {
                    svals[tid] = v2;  sidx[tid] = i2;
                }
            }
            __syncthreads();
        }
        const int tidx = sidx[0];

        // ---- boundary-condition loss: thread b handles batch b ----
        const float* pr = pred  + ((size_t)tid * Nn + tidx) * SD;
        const float* tr = truev + ((size_t)tid * Nn + tidx) * SD;
        #pragma unroll
        for (int i = 0; i < SD; i++) {
            float d = pr[i] - tr[i];
            sBC = fmaf(d, d, sBC);
        }
    } else {
        // ---- tile workers ----
        const int wid = blockIdx.x - 1;

        float4 p[4];
        float  hlo = 0.f, hhi = 0.f;
        load_pred(wid, pred, tid, p, hlo, hhi);

        #pragma unroll 1
        for (int tile = wid; tile < NTILES; tile += WORKERS) {
            __syncthreads();                    // buf free (prev FD done)
            store_pred(buf, tid, p, hlo, hhi);

            const int chunk = tile & (CHUNKS - 1);
            const int n0    = chunk * ROWS;
            const size_t rowoff = ((size_t)(tile >> 5) * Nn + n0);

            // true + control for THIS tile (demand; 32 warps/SM hide it)
            const float4* t4g = (const float4*)(truev + rowoff * SD);
            float4 tt[4];
            tt[0] = t4g[tid];
            tt[1] = t4g[tid + 256];
            tt[2] = t4g[tid + 512];
            if (tid < TILE_F4 - 768) tt[3] = t4g[tid + 768];
            const float4 u4 = ((const float4*)(ctrl + rowoff * 4))[tid];

            // ---- weighted data loss (p regs reused before overwrite) ----
            #pragma unroll
            for (int j = 0; j < 4; j++) {
                const int i = tid + j * 256;
                if (j == 3 && i >= TILE_F4) break;
                unsigned e = 4u * (unsigned)i;
                unsigned r = e / 14u;
                unsigned c = e - r * 14u;
                const float pe[4] = { p[j].x, p[j].y, p[j].z, p[j].w };
                const float te[4] = { tt[j].x, tt[j].y, tt[j].z, tt[j].w };
                #pragma unroll
                for (int k = 0; k < 4; k++) {
                    float d = pe[k] - te[k];
                    float w = (c < 6u) ? (1.0f / 6.0f)
                            : ((c == 13u) ? 1.0f : (1.0f / 7.0f));
                    wD = fmaf(d * d, w, wD);
                    if (++c == 14u) { c = 0u; ++r; }
                }
            }

            // ---- prefetch next tile's pred (in flight across FD phase) ----
            if (tile + WORKERS < NTILES) {
                hlo = hhi = 0.f;
                load_pred(tile + WORKERS, pred, tid, p, hlo, hhi);
            }

            __syncthreads();                    // buf filled

            // ---- per-row physics from smem (no arrays; scalars only) ----
            const int n = n0 + tid;
            const float* s = buf + tid * SD;

            const bool fwd = (n == 0), bwd = (n == Nn - 1);
            const float* hip = (tid < ROWS - 1) ? (buf + (tid + 1) * SD)
                                                : (buf + HALO_HI_OFF);
            const float* lop = (tid > 0)        ? (buf + (tid - 1) * SD)
                                                : (buf + HALO_LO_OFF);
            if (fwd) lop = s;
            if (bwd) hip = s;

            float ta, tb2;
            if (fwd)      { ta = t[0];      tb2 = t[1];      }
            else if (bwd) { ta = t[Nn - 2]; tb2 = t[Nn - 1]; }
            else          { ta = t[n - 1];  tb2 = t[n + 1];  }
            const float inv_dt = 1.0f / (tb2 - ta + 1e-12f);

            // scalars from own row
            const float2 s34   = lds2(s, 3);   // vx (pair 2..3 crosses; load individually aligned)
            // rows are 8B aligned at even offsets only -> use explicit pairs:
            // s[0..13]: pairs (0,1)(2,3)(4,5)(6,7)(8,9)(10,11)(12,13)
            const float2 s01 = lds2(s, 0);
            const float2 s23 = lds2(s, 2);
            const float2 s45 = lds2(s, 4);
            const float2 s67 = lds2(s, 6);
            const float2 s89 = lds2(s, 8);
            const float2 sAB = lds2(s, 10);
            const float2 sCD = lds2(s, 12);
            (void)s34;
            const float vx = s23.y, vy = s45.x, vz = s45.y;
            const float q0 = s67.x, q1 = s67.y, q2 = s89.x, q3 = s89.y;
            const float wx = sAB.x, wy = sAB.y, wz = sCD.x;
            const float m  = sCD.y;

            // quaternion norm loss
            const float qn  = sqrtf(q0 * q0 + q1 * q1 + q2 * q2 + q3 * q3);
            const float dqn = qn - 1.0f;
            sQ += dqn * dqn;

            // shared dynamics scalars
            const float thrust = u4.x * 1000000.0f;
            const float bzx = 2.0f * (q1 * q3 + q0 * q2);
            const float bzy = 2.0f * (q2 * q3 - q0 * q1);
            const float bzz = 1.0f - 2.0f * (q1 * q1 + q2 * q2);
            const float speed = sqrtf(vx * vx + vy * vy + vz * vz + 1e-12f);
            const float dragc = -0.30625f * speed;
            const float invm  = 1.0f / m;

            float sPl = 0.f;
            float rr;
            // i = 0..1
            {   float2 h = lds2(hip, 0), l = lds2(lop, 0);
                rr = (h.x - l.x) * inv_dt - vx;  sPl = fmaf(rr, rr, sPl);
                rr = (h.y - l.y) * inv_dt - vy;  sPl = fmaf(rr, rr, sPl); }
            // i = 2..3
            {   float2 h = lds2(hip, 2), l = lds2(lop, 2);
                rr = (h.x - l.x) * inv_dt - vz;  sPl = fmaf(rr, rr, sPl);
                rr = (h.y - l.y) * inv_dt - (thrust * bzx + dragc * vx) * invm;
                sPl = fmaf(rr, rr, sPl); }
            // i = 4..5
            {   float2 h = lds2(hip, 4), l = lds2(lop, 4);
                rr = (h.x - l.x) * inv_dt - (thrust * bzy + dragc * vy) * invm;
                sPl = fmaf(rr, rr, sPl);
                rr = (h.y - l.y) * inv_dt - ((thrust * bzz + dragc * vz) * invm - 9.80665f);
                sPl = fmaf(rr, rr, sPl); }
            // i = 6..7
            {   float2 h = lds2(hip, 6), l = lds2(lop, 6);
                rr = (h.x - l.x) * inv_dt - 0.5f * (-q1 * wx - q2 * wy - q3 * wz);
                sPl = fmaf(rr, rr, sPl);
                rr = (h.y - l.y) * inv_dt - 0.5f * ( q0 * wx + q2 * wz - q3 * wy);
                sPl = fmaf(rr, rr, sPl); }
            // i = 8..9
            {   float2 h = lds2(hip, 8), l = lds2(lop, 8);
                rr = (h.x - l.x) * inv_dt - 0.5f * ( q0 * wy - q1 * wz + q3 * wx);
                sPl = fmaf(rr, rr, sPl);
                rr = (h.y - l.y) * inv_dt - 0.5f * ( q0 * wz + q1 * wy - q2 * wx);
                sPl = fmaf(rr, rr, sPl); }
            // i = 10..11
            {   float2 h = lds2(hip, 10), l = lds2(lop, 10);
                rr = (h.x - l.x) * inv_dt
                   - (u4.y * 10000.0f + 4000.0f * wy * wz) * (1.0f / 5000.0f);
                sPl = fmaf(rr, rr, sPl);
                rr = (h.y - l.y) * inv_dt
                   - (u4.z * 10000.0f - 4000.0f * wz * wx) * (1.0f / 5000.0f);
                sPl = fmaf(rr, rr, sPl); }
            // i = 12..13
            {   float2 h = lds2(hip, 12), l = lds2(lop, 12);
                rr = (h.x - l.x) * inv_dt - (u4.w * 10000.0f) * (1.0f / 1000.0f);
                sPl = fmaf(rr, rr, sPl);
                rr = (h.y - l.y) * inv_dt - (-thrust * (1.0f / (300.0f * 9.80665f)));
                sPl = fmaf(rr, rr, sPl);
                // mass flow loss: hip[13] == m[n+1] whenever n < Nn-1
                if (n < Nn - 1) {
                    float dmf = h.y - m;
                    if (dmf > 0.f) sMF += dmf;
                } }
            sP += sPl;
        }
    }

    // ---- reduction: fp32 intra-warp, fp64 cross-warp + global atomics ----
    float vf[5] = { wD, sP, sQ, sMF, sBC };
    const int lane = tid & 31, warp = tid >> 5;
    #pragma unroll
    for (int off = 16; off > 0; off >>= 1)
        #pragma unroll
        for (int j = 0; j < 5; j++)
            vf[j] += __shfl_down_sync(0xffffffffu, vf[j], off);
    if (lane == 0)
        #pragma unroll
        for (int j = 0; j < 5; j++) red[warp][j] = (double)vf[j];
    __syncthreads();

    if (warp == 0) {
        double vd[5];
        #pragma unroll
        for (int j = 0; j < 5; j++)
            vd[j] = (lane < THREADS / 32) ? red[lane][j] : 0.0;
        #pragma unroll
        for (int off = 4; off > 0; off >>= 1)
            #pragma unroll
            for (int j = 0; j < 5; j++)
                vd[j] += __shfl_down_sync(0xffffffffu, vd[j], off);
        if (lane == 0) {
            #pragma unroll
            for (int j = 0; j < 5; j++)
                atomicAdd(&g_acc[j], vd[j]);

            __threadfence();
            unsigned int ticket = atomicAdd(&g_done, 1u);
            if (ticket == GRID - 1) {
                const double BN = (double)Bb * (double)Nn;
                double L_data = g_acc[0] / BN;
                double L_phys = g_acc[1] / (BN * 14.0);
                double L_quat = g_acc[2] / BN;
                double L_mf   = g_acc[3] / ((double)Bb * (double)(Nn - 1));
                double L_bc   = g_acc[4] / ((double)Bb * 14.0);
                double total  = L_data + 0.1 * L_phys + L_bc
                              + 0.01 * L_quat + 0.01 * L_mf;
                out[0] = (float)total;
                out[1] = (float)L_data;
                out[2] = (float)L_phys;
                out[3] = (float)L_bc;
                out[4] = (float)L_quat;
                out[5] = (float)L_mf;
                // reset for next graph replay
                #pragma unroll
                for (int j = 0; j < 5; j++) g_acc[j] = 0.0;
                g_done = 0u;
            }
        }
    }
}

// ---------------------------------------------------------------------------
extern "C" void kernel_launch(void* const* d_in, const int* in_sizes, int n_in,
                              void* d_out, int out_size)
{
    const float* pred = (const float*)d_in[0];
    const float* tru  = (const float*)d_in[1];
    const float* t    = (const float*)d_in[2];
    const float* ctrl = (const float*)d_in[3];
    float* out = (float*)d_out;

    k_main<<<GRID, THREADS>>>(pred, tru, t, ctrl, out);
}

// round 17
// speedup vs baseline: 1.2354x; 1.2022x over previous
#include <cuda_runtime.h>
#include <math.h>

#define Bb      256
#define Nn      8192
#define SD      14
#define ROWS    256
#define THREADS 256
#define CHUNKS  32
#define NTILES  (Bb * CHUNKS)     // 8192
#define GRID    444               // 3 blocks/SM; block 0 = argmin+BC
#define WORKERS (GRID - 1)        // 443

#define TILE_F4      ((ROWS * SD) / 4)   // 896
#define MAIN_FLOATS  (ROWS * SD)         // 3584
#define HALO_LO_OFF  MAIN_FLOATS         // 3584 (14 floats)
#define HALO_HI_OFF  (MAIN_FLOATS + 14)  // 3598
#define BUF_FLOATS   3616                // 16B-multiple

// accumulators: 0=weighted data, 1=phys, 2=quat, 3=massflow, 4=bc
__device__ double       g_acc[5];
__device__ unsigned int g_done;

// ---------------------------------------------------------------------------
__device__ __forceinline__ void cp16(void* smem_dst, const void* gsrc) {
    unsigned sa = (unsigned)__cvta_generic_to_shared(smem_dst);
    asm volatile("cp.async.cg.shared.global [%0], [%1], 16;\n" :: "r"(sa), "l"(gsrc));
}
__device__ __forceinline__ void cp4(void* smem_dst, const void* gsrc) {
    unsigned sa = (unsigned)__cvta_generic_to_shared(smem_dst);
    asm volatile("cp.async.ca.shared.global [%0], [%1], 4;\n" :: "r"(sa), "l"(gsrc));
}
#define CP_COMMIT() asm volatile("cp.async.commit_group;\n" ::: "memory")
#define CP_WAIT1()  asm volatile("cp.async.wait_group 1;\n" ::: "memory")

// cp.async part of a pred tile: f4 indices [0,768) + both halo rows.
// Always commits exactly one group (uniform count across all tiles/threads).
__device__ __forceinline__ void issue_cp(int tile, float* stage,
                                         const float* __restrict__ pred, int tid)
{
    if (tile < NTILES) {
        const int b = tile >> 5, chunk = tile & (CHUNKS - 1);
        const size_t base = ((size_t)b * Nn + (size_t)chunk * ROWS) * SD;
        const float4* p4 = (const float4*)(pred + base);
        float4* b4 = (float4*)stage;
        cp16(b4 + tid,       p4 + tid);
        cp16(b4 + tid + 256, p4 + tid + 256);
        cp16(b4 + tid + 512, p4 + tid + 512);
        if (chunk > 0 && tid >= 128 && tid < 128 + SD)
            cp4(stage + HALO_LO_OFF + (tid - 128), pred + base - SD + (tid - 128));
        if (chunk < CHUNKS - 1 && tid >= 160 && tid < 160 + SD)
            cp4(stage + HALO_HI_OFF + (tid - 160), pred + base + MAIN_FLOATS + (tid - 160));
    }
    CP_COMMIT();
}

__device__ __forceinline__ float2 lds2(const float* p, int i) {
    return *(const float2*)(p + i);
}

// ---------------------------------------------------------------------------
// Persistent kernel: dual-engine streaming.
//   cp.async : pred f4 [0,768) + halos          (~84 MB, LDGSTS pipe)
//   demand   : true + ctrl + pred f4 [768,896)  (~168 MB, LSU pipe)
// ---------------------------------------------------------------------------
__global__ __launch_bounds__(THREADS, 3)
void k_main(const float* __restrict__ pred,
            const float* __restrict__ truev,
            const float* __restrict__ t,
            const float* __restrict__ ctrl,
            float* __restrict__ out)
{
    __shared__ __align__(16) float sm2[2][BUF_FLOATS];
    __shared__ double red[THREADS / 32][5];

    const int tid = threadIdx.x;
    float wD = 0.f, sP = 0.f, sQ = 0.f, sMF = 0.f, sBC = 0.f;

    if (blockIdx.x == 0) {
        // ---- argmin |t[0,:,0]| ----
        __shared__ float svals[THREADS];
        __shared__ int   sidx[THREADS];
        const float4* t4 = (const float4*)t;
        float best = 3.402823466e+38f;
        int   bi   = 0;
        #pragma unroll
        for (int j = 0; j < 8; j++) {
            float4 v = t4[tid * 8 + j];
            float a[4] = { fabsf(v.x), fabsf(v.y), fabsf(v.z), fabsf(v.w) };
            #pragma unroll
            for (int k = 0; k < 4; k++) {
                int idx = tid * 32 + j * 4 + k;
                if (a[k] < best) { best = a[k]; bi = idx; }
            }
        }
        svals[tid] = best;  sidx[tid] = bi;
        __syncthreads();
        for (int s = THREADS / 2; s > 0; s >>= 1) {
            if (tid < s) {
                float v2 = svals[tid + s];
                int   i2 = sidx[tid + s];
                if (v2 < svals[tid] || (v2 == svals[tid] && i2 < sidx[tid])) {
                    svals[tid] = v2;  sidx[tid] = i2;
                }
            }
            __syncthreads();
        }
        const int tidx = sidx[0];

        // ---- boundary-condition loss: thread b handles batch b ----
        const float* pr = pred  + ((size_t)tid * Nn + tidx) * SD;
        const float* tr = truev + ((size_t)tid * Nn + tidx) * SD;
        #pragma unroll
        for (int i = 0; i < SD; i++) {
            float d = pr[i] - tr[i];
            sBC = fmaf(d, d, sBC);
        }
    } else {
        // ---- tile workers ----
        const int wid = blockIdx.x - 1;

        issue_cp(wid,           sm2[0], pred, tid);   // group for stage 0
        issue_cp(wid + WORKERS, sm2[1], pred, tid);   // group for stage 1
        int stage = 0;

        #pragma unroll 1
        for (int tile = wid; tile < NTILES; tile += WORKERS) {
            CP_WAIT1();                       // this tile's cp.async group done
            float* buf = sm2[stage];

            const int chunk = tile & (CHUNKS - 1);
            const int n0    = chunk * ROWS;
            const size_t rowoff = ((size_t)(tile >> 5) * Nn + n0);

            // demand loads: pred tail f4, true, ctrl
            float4 p3 = make_float4(0.f, 0.f, 0.f, 0.f);
            if (tid < TILE_F4 - 768)
                p3 = ((const float4*)(pred + rowoff * SD))[768 + tid];
            const float4* t4g = (const float4*)(truev + rowoff * SD);
            float4 tt[4];
            tt[0] = t4g[tid];
            tt[1] = t4g[tid + 256];
            tt[2] = t4g[tid + 512];
            if (tid < TILE_F4 - 768) tt[3] = t4g[tid + 768];
            const float4 u4 = ((const float4*)(ctrl + rowoff * 4))[tid];

            // ---- weighted data loss ----
            // j<3: pred from own cp.async-written smem slots (self-visible
            // after wait_group); j==3: pred from demand register.
            #pragma unroll
            for (int j = 0; j < 4; j++) {
                const int i = tid + j * 256;
                if (j == 3 && i >= TILE_F4) break;
                float4 pv = (j < 3) ? ((const float4*)buf)[i] : p3;
                unsigned e = 4u * (unsigned)i;
                unsigned r = e / 14u;
                unsigned c = e - r * 14u;
                const float pe[4] = { pv.x, pv.y, pv.z, pv.w };
                const float te[4] = { tt[j].x, tt[j].y, tt[j].z, tt[j].w };
                #pragma unroll
                for (int k = 0; k < 4; k++) {
                    float d = pe[k] - te[k];
                    float w = (c < 6u) ? (1.0f / 6.0f)
                            : ((c == 13u) ? 1.0f : (1.0f / 7.0f));
                    wD = fmaf(d * d, w, wD);
                    if (++c == 14u) { c = 0u; ++r; }
                }
            }

            // complete the smem tile with the demand-loaded tail
            if (tid < TILE_F4 - 768)
                ((float4*)buf)[768 + tid] = p3;
            __syncthreads();                  // tile complete & published

            // ---- per-row physics from smem (scalarized) ----
            const int n = n0 + tid;
            const float* s = buf + tid * SD;

            const bool fwd = (n == 0), bwd = (n == Nn - 1);
            const float* hip = (tid < ROWS - 1) ? (buf + (tid + 1) * SD)
                                                : (buf + HALO_HI_OFF);
            const float* lop = (tid > 0)        ? (buf + (tid - 1) * SD)
                                                : (buf + HALO_LO_OFF);
            if (fwd) lop = s;
            if (bwd) hip = s;

            float ta, tb2;
            if (fwd)      { ta = t[0];      tb2 = t[1];      }
            else if (bwd) { ta = t[Nn - 2]; tb2 = t[Nn - 1]; }
            else          { ta = t[n - 1];  tb2 = t[n + 1];  }
            const float inv_dt = 1.0f / (tb2 - ta + 1e-12f);

            const float2 s23 = lds2(s, 2);
            const float2 s45 = lds2(s, 4);
            const float2 s67 = lds2(s, 6);
            const float2 s89 = lds2(s, 8);
            const float2 sAB = lds2(s, 10);
            const float2 sCD = lds2(s, 12);
            const float vx = s23.y, vy = s45.x, vz = s45.y;
            const float q0 = s67.x, q1 = s67.y, q2 = s89.x, q3 = s89.y;
            const float wx = sAB.x, wy = sAB.y, wz = sCD.x;
            const float m  = sCD.y;

            const float qn  = sqrtf(q0 * q0 + q1 * q1 + q2 * q2 + q3 * q3);
            const float dqn = qn - 1.0f;
            sQ += dqn * dqn;

            const float thrust = u4.x * 1000000.0f;
            const float bzx = 2.0f * (q1 * q3 + q0 * q2);
            const float bzy = 2.0f * (q2 * q3 - q0 * q1);
            const float bzz = 1.0f - 2.0f * (q1 * q1 + q2 * q2);
            const float speed = sqrtf(vx * vx + vy * vy + vz * vz + 1e-12f);
            const float dragc = -0.30625f * speed;
            const float invm  = 1.0f / m;

            float sPl = 0.f;
            float rr;
            {   float2 h = lds2(hip, 0), l = lds2(lop, 0);
                rr = (h.x - l.x) * inv_dt - vx;  sPl = fmaf(rr, rr, sPl);
                rr = (h.y - l.y) * inv_dt - vy;  sPl = fmaf(rr, rr, sPl); }
            {   float2 h = lds2(hip, 2), l = lds2(lop, 2);
                rr = (h.x - l.x) * inv_dt - vz;  sPl = fmaf(rr, rr, sPl);
                rr = (h.y - l.y) * inv_dt - (thrust * bzx + dragc * vx) * invm;
                sPl = fmaf(rr, rr, sPl); }
            {   float2 h = lds2(hip, 4), l = lds2(lop, 4);
                rr = (h.x - l.x) * inv_dt - (thrust * bzy + dragc * vy) * invm;
                sPl = fmaf(rr, rr, sPl);
                rr = (h.y - l.y) * inv_dt - ((thrust * bzz + dragc * vz) * invm - 9.80665f);
                sPl = fmaf(rr, rr, sPl); }
            {   float2 h = lds2(hip, 6), l = lds2(lop, 6);
                rr = (h.x - l.x) * inv_dt - 0.5f * (-q1 * wx - q2 * wy - q3 * wz);
                sPl = fmaf(rr, rr, sPl);
                rr = (h.y - l.y) * inv_dt - 0.5f * ( q0 * wx + q2 * wz - q3 * wy);
                sPl = fmaf(rr, rr, sPl); }
            {   float2 h = lds2(hip, 8), l = lds2(lop, 8);
                rr = (h.x - l.x) * inv_dt - 0.5f * ( q0 * wy - q1 * wz + q3 * wx);
                sPl = fmaf(rr, rr, sPl);
                rr = (h.y - l.y) * inv_dt - 0.5f * ( q0 * wz + q1 * wy - q2 * wx);
                sPl = fmaf(rr, rr, sPl); }
            {   float2 h = lds2(hip, 10), l = lds2(lop, 10);
                rr = (h.x - l.x) * inv_dt
                   - (u4.y * 10000.0f + 4000.0f * wy * wz) * (1.0f / 5000.0f);
                sPl = fmaf(rr, rr, sPl);
                rr = (h.y - l.y) * inv_dt
                   - (u4.z * 10000.0f - 4000.0f * wz * wx) * (1.0f / 5000.0f);
                sPl = fmaf(rr, rr, sPl); }
            {   float2 h = lds2(hip, 12), l = lds2(lop, 12);
                rr = (h.x - l.x) * inv_dt - (u4.w * 10000.0f) * (1.0f / 1000.0f);
                sPl = fmaf(rr, rr, sPl);
                rr = (h.y - l.y) * inv_dt - (-thrust * (1.0f / (300.0f * 9.80665f)));
                sPl = fmaf(rr, rr, sPl);
                if (n < Nn - 1) {
                    float dmf = h.y - m;
                    if (dmf > 0.f) sMF += dmf;
                } }
            sP += sPl;

            __syncthreads();                  // all FD reads of buf done
            issue_cp(tile + 2 * WORKERS, buf, pred, tid);   // refill this stage
            stage ^= 1;
        }
    }

    // ---- reduction: fp32 intra-warp, fp64 cross-warp + global atomics ----
    float vf[5] = { wD, sP, sQ, sMF, sBC };
    const int lane = tid & 31, warp = tid >> 5;
    #pragma unroll
    for (int off = 16; off > 0; off >>= 1)
        #pragma unroll
        for (int j = 0; j < 5; j++)
            vf[j] += __shfl_down_sync(0xffffffffu, vf[j], off);
    if (lane == 0)
        #pragma unroll
        for (int j = 0; j < 5; j++) red[warp][j] = (double)vf[j];
    __syncthreads();

    if (warp == 0) {
        double vd[5];
        #pragma unroll
        for (int j = 0; j < 5; j++)
            vd[j] = (lane < THREADS / 32) ? red[lane][j] : 0.0;
        #pragma unroll
        for (int off = 4; off > 0; off >>= 1)
            #pragma unroll
            for (int j = 0; j < 5; j++)
                vd[j] += __shfl_down_sync(0xffffffffu, vd[j], off);
        if (lane == 0) {
            #pragma unroll
            for (int j = 0; j < 5; j++)
                atomicAdd(&g_acc[j], vd[j]);

            __threadfence();
            unsigned int ticket = atomicAdd(&g_done, 1u);
            if (ticket == GRID - 1) {
                const double BN = (double)Bb * (double)Nn;
                double L_data = g_acc[0] / BN;
                double L_phys = g_acc[1] / (BN * 14.0);
                double L_quat = g_acc[2] / BN;
                double L_mf   = g_acc[3] / ((double)Bb * (double)(Nn - 1));
                double L_bc   = g_acc[4] / ((double)Bb * 14.0);
                double total  = L_data + 0.1 * L_phys + L_bc
                              + 0.01 * L_quat + 0.01 * L_mf;
                out[0] = (float)total;
                out[1] = (float)L_data;
                out[2] = (float)L_phys;
                out[3] = (float)L_bc;
                out[4] = (float)L_quat;
                out[5] = (float)L_mf;
                // reset for next graph replay
                #pragma unroll
                for (int j = 0; j < 5; j++) g_acc[j] = 0.0;
                g_done = 0u;
            }
        }
    }
}

// ---------------------------------------------------------------------------
extern "C" void kernel_launch(void* const* d_in, const int* in_sizes, int n_in,
                              void* d_out, int out_size)
{
    const float* pred = (const float*)d_in[0];
    const float* tru  = (const float*)d_in[1];
    const float* t    = (const float*)d_in[2];
    const float* ctrl = (const float*)d_in[3];
    float* out = (float*)d_out;

    k_main<<<GRID, THREADS>>>(pred, tru, t, ctrl, out);
}